// round 6
// baseline (speedup 1.0000x reference)
#include <cuda_runtime.h>
#include <cuda_bf16.h>

// Fused 2-layer LSTM (pipelined L2(t-1) || L1(t)) + time-softmax(last) +
// dense head + softmax. One warp per batch element.
// bf16x2 weights/h/x, fp32 cell + activations. Register-optimized for
// 5 CTAs/SM: streamed h-vector consumption + bias folded into chain init.

#define FULLMASK 0xffffffffu
#define LOG2E 1.4426950408889634f

typedef unsigned int u32;

static __device__ __forceinline__ u32 hfma2b(u32 a, u32 b, u32 c) {
    u32 d;
    asm("fma.rn.bf16x2 %0, %1, %2, %3;" : "=r"(d) : "r"(a), "r"(b), "r"(c));
    return d;
}
static __device__ __forceinline__ u32 haddb2(u32 a, u32 b) {
    u32 d;
    asm("add.rn.bf16x2 %0, %1, %2;" : "=r"(d) : "r"(a), "r"(b));
    return d;
}
// pack two f32 -> bf16x2 {lo, hi}
static __device__ __forceinline__ u32 packb2(float lo, float hi) {
    u32 d;
    asm("cvt.rn.bf16x2.f32 %0, %1, %2;" : "=r"(d) : "f"(hi), "f"(lo));
    return d;
}
static __device__ __forceinline__ float2 unpackb2(u32 v) {
    __nv_bfloat162 h = *reinterpret_cast<__nv_bfloat162*>(&v);
    return make_float2(__low2float(h), __high2float(h));
}
static __device__ __forceinline__ float ex2f(float x) {
    float y; asm("ex2.approx.f32 %0, %1;" : "=f"(y) : "f"(x)); return y;
}
static __device__ __forceinline__ float rcpf(float x) {
    float y; asm("rcp.approx.f32 %0, %1;" : "=f"(y) : "f"(x)); return y;
}
static __device__ __forceinline__ float tanhap(float x) {
    float y; asm("tanh.approx.f32 %0, %1;" : "=f"(y) : "f"(x)); return y;
}

// consume one uint4 of bf16x2 vector pairs into split accumulators
#define BQ4(W, OFF, A0, A1, V) do {                                       \
    A0 = hfma2b((W)[(OFF) + 0], (V).x, A0);                               \
    A1 = hfma2b((W)[(OFF) + 1], (V).y, A1);                               \
    A0 = hfma2b((W)[(OFF) + 2], (V).z, A0);                               \
    A1 = hfma2b((W)[(OFF) + 3], (V).w, A1);                               \
} while (0)

// merge split bf16x2 accumulators -> f32 gate value
#define BMERGE(A0, A1, G) do {                                            \
    float2 f_ = unpackb2(haddb2(A0, A1));                                 \
    G = f_.x + f_.y;                                                      \
} while (0)

// merged gates -> activations -> cell update -> hidden (valid on lanes<16)
#define GATESG(GLO, GHI, CC, HOUT) do {                                   \
    float sA_ = fmaf(0.5f, tanhap(0.5f * (GLO)), 0.5f);                   \
    float tA_ = fmaf(cS, tanhap(cS * (GHI)), cB);                         \
    float fg_ = __shfl_down_sync(FULLMASK, sA_, 16);                      \
    float og_ = __shfl_down_sync(FULLMASK, tA_, 16);                      \
    CC = fmaf(fg_, CC, sA_ * tA_);                                        \
    HOUT = og_ * tanhap(CC);                                              \
} while (0)

// pack h (lanes<16, fp32) into 8 bf16x2 pairs at BUF (u32*)
#define STORE_HPAIRS(HV, BUF) do {                                        \
    float hb_ = __shfl_down_sync(FULLMASK, HV, 1);                        \
    if (loG && !(lane & 1)) (BUF)[lane >> 1] = packb2(HV, hb_);           \
} while (0)

__global__ void __launch_bounds__(128, 5)
lstm_bf16_kernel(const float* __restrict__ x,
                 const float* __restrict__ Wih1, const float* __restrict__ Whh1,
                 const float* __restrict__ bih1, const float* __restrict__ bhh1,
                 const float* __restrict__ Wih2, const float* __restrict__ Whh2,
                 const float* __restrict__ bih2, const float* __restrict__ bhh2,
                 const float* __restrict__ Wd1, const float* __restrict__ bd1,
                 const float* __restrict__ Wd2, const float* __restrict__ bd2,
                 const float* __restrict__ Wd3, const float* __restrict__ bd3,
                 float* __restrict__ out)
{
    constexpr int T = 512, IN = 11;
    const int lane = threadIdx.x & 31;
    const int wid  = threadIdx.x >> 5;
    const int b    = blockIdx.x * 4 + wid;

    // staging (per warp): x pairs [phase][4 steps][8 u32], h pairs [phase][8 u32]
    __shared__ __align__(16) u32 xstage[4][2][32];
    __shared__ __align__(16) u32 h1buf[4][2][8];
    __shared__ __align__(16) u32 h2buf[4][2][8];

    const int j = lane, jh = lane + 32;

    // ---- packed bf16x2 weights ----
    u32 wi1L[6], wi1H[6];
#pragma unroll
    for (int k = 0; k < 5; ++k) {
        wi1L[k] = packb2(Wih1[j  * IN + 2 * k], Wih1[j  * IN + 2 * k + 1]);
        wi1H[k] = packb2(Wih1[jh * IN + 2 * k], Wih1[jh * IN + 2 * k + 1]);
    }
    wi1L[5] = packb2(Wih1[j  * IN + 10], 0.f);
    wi1H[5] = packb2(Wih1[jh * IN + 10], 0.f);

    u32 wh1L[8], wh1H[8], wi2L[8], wi2H[8], wh2L[8], wh2H[8];
#pragma unroll
    for (int k = 0; k < 8; ++k) {
        wh1L[k] = packb2(Whh1[j  * 16 + 2 * k], Whh1[j  * 16 + 2 * k + 1]);
        wh1H[k] = packb2(Whh1[jh * 16 + 2 * k], Whh1[jh * 16 + 2 * k + 1]);
        wi2L[k] = packb2(Wih2[j  * 16 + 2 * k], Wih2[j  * 16 + 2 * k + 1]);
        wi2H[k] = packb2(Wih2[jh * 16 + 2 * k], Wih2[jh * 16 + 2 * k + 1]);
        wh2L[k] = packb2(Whh2[j  * 16 + 2 * k], Whh2[j  * 16 + 2 * k + 1]);
        wh2H[k] = packb2(Whh2[jh * 16 + 2 * k], Whh2[jh * 16 + 2 * k + 1]);
    }
    // biases folded into chain initializers as bf16x2 {bias, 0}
    const u32 b1Lp = packb2(bih1[j]  + bhh1[j],  0.f);
    const u32 b1Hp = packb2(bih1[jh] + bhh1[jh], 0.f);
    const u32 b2Lp = packb2(bih2[j]  + bhh2[j],  0.f);
    const u32 b2Hp = packb2(bih2[jh] + bhh2[jh], 0.f);

    // hi-gate activation: tanh (g) on lanes<16 (cS=1,cB=0), sigmoid (o) on
    // lanes>=16 (0.5*tanh(0.5x)+0.5). Note cA==cS so one constant serves both.
    const bool loG = (lane < 16);
    const float cS = loG ? 1.0f : 0.5f;
    const float cB = loG ? 0.0f : 0.5f;

    const float* xb = x + (size_t)b * (T * IN);

    // ---- stage chunk 0 (t = 0..3) as bf16x2 pairs ----
    {
        float v[4];
#pragma unroll
        for (int s = 0; s < 4; ++s)
            v[s] = (lane < IN) ? __ldg(xb + s * IN + lane) : 0.f;
#pragma unroll
        for (int s = 0; s < 4; ++s) {
            float hb = __shfl_down_sync(FULLMASK, v[s], 1);
            if (lane < IN && !(lane & 1))
                xstage[wid][0][s * 8 + (lane >> 1)] = packb2(v[s], hb);
        }
    }
    if (loG && !(lane & 1)) h2buf[wid][1][lane >> 1] = 0;   // h2(-1), phase 1
    __syncwarp();

    float cc1 = 0.f, cc2 = 0.f, h2 = 0.f, ssum = 0.f;

    // ---- prologue: h1(0) from x(0) alone (h0 = 0) ----
    {
        const u32* xr = &xstage[wid][0][0];
        u32 tL0 = b1Lp, tL1 = 0, tH0 = b1Hp, tH1 = 0;
        uint4 xa = *(const uint4*)xr;
        BQ4(wi1L, 0, tL0, tL1, xa);
        BQ4(wi1H, 0, tH0, tH1, xa);
        uint2 xc = *(const uint2*)(xr + 4);
        tL0 = hfma2b(wi1L[4], xc.x, tL0); tL1 = hfma2b(wi1L[5], xc.y, tL1);
        tH0 = hfma2b(wi1H[4], xc.x, tH0); tH1 = hfma2b(wi1H[5], xc.y, tH1);
        float gLo, gHi;
        BMERGE(tL0, tL1, gLo);
        BMERGE(tH0, tH1, gHi);
        float h1v;
        GATESG(gLo, gHi, cc1, h1v);
        STORE_HPAIRS(h1v, &h1buf[wid][0][0]);
    }
    __syncwarp();

    // ---- main loop: chunks of 4 steps; iter does L2(t-1) || L1(t) ----
    for (int c = 0; c < 128; ++c) {
        // prefetch next chunk's x into registers (consumed >= 4 steps later)
        float px0, px1, px2, px3;
        px0 = px1 = px2 = px3 = 0.f;
        if (c < 127 && lane < IN) {
            const float* xp = xb + (4 * (c + 1)) * IN + lane;
            px0 = __ldg(xp);
            px1 = __ldg(xp + IN);
            px2 = __ldg(xp + 2 * IN);
            px3 = __ldg(xp + 3 * IN);
        }
        const u32* xs = &xstage[wid][c & 1][0];

#pragma unroll
        for (int s = 0; s < 4; ++s) {
            const int t = 4 * c + s;
            if (c == 0 && s == 0) continue;   // t=0 handled in prologue
            const int i = t - 1;
            const int pi = i & 1, pn = pi ^ 1;

            // L2(i) accumulators and L1(t) accumulators (all independent)
            u32 sL0 = b2Lp, sL1 = 0, sH0 = b2Hp, sH1 = 0;
            u32 tL0 = b1Lp, tL1 = 0, tH0 = b1Hp, tH1 = 0;

            // stream h1(i): feeds wi2 (L2) and wh1 (L1)
            {
                const uint4* hp = (const uint4*)(&h1buf[wid][pi][0]);
                uint4 ha = hp[0];
                BQ4(wi2L, 0, sL0, sL1, ha); BQ4(wi2H, 0, sH0, sH1, ha);
                BQ4(wh1L, 0, tL0, tL1, ha); BQ4(wh1H, 0, tH0, tH1, ha);
                uint4 hb = hp[1];
                BQ4(wi2L, 4, sL0, sL1, hb); BQ4(wi2H, 4, sH0, sH1, hb);
                BQ4(wh1L, 4, tL0, tL1, hb); BQ4(wh1H, 4, tH0, tH1, hb);
            }
            // stream h2(i-1): feeds wh2 (L2)
            {
                const uint4* qp = (const uint4*)(&h2buf[wid][pn][0]);
                uint4 qa = qp[0];
                BQ4(wh2L, 0, sL0, sL1, qa); BQ4(wh2H, 0, sH0, sH1, qa);
                uint4 qb = qp[1];
                BQ4(wh2L, 4, sL0, sL1, qb); BQ4(wh2H, 4, sH0, sH1, qb);
            }
            // stream x(t): feeds wi1 (L1)
            {
                const u32* xr = xs + s * 8;
                uint4 xa = *(const uint4*)xr;
                BQ4(wi1L, 0, tL0, tL1, xa);
                BQ4(wi1H, 0, tH0, tH1, xa);
                uint2 xc = *(const uint2*)(xr + 4);
                tL0 = hfma2b(wi1L[4], xc.x, tL0); tL1 = hfma2b(wi1L[5], xc.y, tL1);
                tH0 = hfma2b(wi1H[4], xc.x, tH0); tH1 = hfma2b(wi1H[5], xc.y, tH1);
            }

            // L2 gates -> h2(i)
            {
                float gLo, gHi;
                BMERGE(sL0, sL1, gLo);
                BMERGE(sH0, sH1, gHi);
                GATESG(gLo, gHi, cc2, h2);
                STORE_HPAIRS(h2, &h2buf[wid][pi][0]);
                ssum += ex2f(h2 * LOG2E);  // h2 in (-1,1): max-free accumulation
            }
            // L1 gates -> h1(t)
            {
                float gLo, gHi;
                BMERGE(tL0, tL1, gLo);
                BMERGE(tH0, tH1, gHi);
                float h1v;
                GATESG(gLo, gHi, cc1, h1v);
                STORE_HPAIRS(h1v, &h1buf[wid][pn][0]);
            }
            __syncwarp();
        }

        // commit prefetched x (packed bf16x2) to the other stage buffer
        {
            const int ph = (c + 1) & 1;
            float hbv;
            hbv = __shfl_down_sync(FULLMASK, px0, 1);
            if (c < 127 && lane < IN && !(lane & 1))
                xstage[wid][ph][0 * 8 + (lane >> 1)] = packb2(px0, hbv);
            hbv = __shfl_down_sync(FULLMASK, px1, 1);
            if (c < 127 && lane < IN && !(lane & 1))
                xstage[wid][ph][1 * 8 + (lane >> 1)] = packb2(px1, hbv);
            hbv = __shfl_down_sync(FULLMASK, px2, 1);
            if (c < 127 && lane < IN && !(lane & 1))
                xstage[wid][ph][2 * 8 + (lane >> 1)] = packb2(px2, hbv);
            hbv = __shfl_down_sync(FULLMASK, px3, 1);
            if (c < 127 && lane < IN && !(lane & 1))
                xstage[wid][ph][3 * 8 + (lane >> 1)] = packb2(px3, hbv);
        }
        __syncwarp();
    }

    // ---- epilogue: L2(T-1) ----
    {
        const int pi = (T - 1) & 1, pn = pi ^ 1;
        u32 sL0 = b2Lp, sL1 = 0, sH0 = b2Hp, sH1 = 0;
        {
            const uint4* hp = (const uint4*)(&h1buf[wid][pi][0]);
            uint4 ha = hp[0];
            BQ4(wi2L, 0, sL0, sL1, ha); BQ4(wi2H, 0, sH0, sH1, ha);
            uint4 hb = hp[1];
            BQ4(wi2L, 4, sL0, sL1, hb); BQ4(wi2H, 4, sH0, sH1, hb);
        }
        {
            const uint4* qp = (const uint4*)(&h2buf[wid][pn][0]);
            uint4 qa = qp[0];
            BQ4(wh2L, 0, sL0, sL1, qa); BQ4(wh2H, 0, sH0, sH1, qa);
            uint4 qb = qp[1];
            BQ4(wh2L, 4, sL0, sL1, qb); BQ4(wh2H, 4, sH0, sH1, qb);
        }
        float gLo, gHi;
        BMERGE(sL0, sL1, gLo);
        BMERGE(sH0, sH1, gHi);
        GATESG(gLo, gHi, cc2, h2);
        ssum += ex2f(h2 * LOG2E);
    }

    // ---- dense head (fp32): s = exp(h2_last)/ssum, 3 tiny GEMVs, softmax ----
    float sval = ex2f(h2 * LOG2E) * rcpf(ssum);   // valid on lanes 0..15
    const int j8 = lane & 7;
    float d1 = bd1[j8];
#pragma unroll
    for (int k = 0; k < 16; ++k) {
        float sk = __shfl_sync(FULLMASK, sval, k);
        d1 = fmaf(Wd1[j8 * 16 + k], sk, d1);
    }
    float d2 = bd2[j8];
#pragma unroll
    for (int k = 0; k < 8; ++k) {
        float dk = __shfl_sync(FULLMASK, d1, k);
        d2 = fmaf(Wd2[j8 * 8 + k], dk, d2);
    }
    const int j3 = (lane < 3) ? lane : 0;
    float d3 = bd3[j3];
#pragma unroll
    for (int k = 0; k < 8; ++k) {
        float dk = __shfl_sync(FULLMASK, d2, k);
        d3 = fmaf(Wd3[j3 * 8 + k], dk, d3);
    }
    float v0 = __shfl_sync(FULLMASK, d3, 0);
    float v1 = __shfl_sync(FULLMASK, d3, 1);
    float v2 = __shfl_sync(FULLMASK, d3, 2);
    float m  = fmaxf(v0, fmaxf(v1, v2));
    float e0 = ex2f((v0 - m) * LOG2E);
    float e1 = ex2f((v1 - m) * LOG2E);
    float e2 = ex2f((v2 - m) * LOG2E);
    float inv = rcpf(e0 + e1 + e2);
    if (lane == 0) {
        out[b * 3 + 0] = e0 * inv;
        out[b * 3 + 1] = e1 * inv;
        out[b * 3 + 2] = e2 * inv;
    }
}

extern "C" void kernel_launch(void* const* d_in, const int* in_sizes, int n_in,
                              void* d_out, int out_size) {
    (void)in_sizes; (void)n_in; (void)out_size;
    const float* x    = (const float*)d_in[0];
    const float* Wih1 = (const float*)d_in[1];
    const float* Whh1 = (const float*)d_in[2];
    const float* bih1 = (const float*)d_in[3];
    const float* bhh1 = (const float*)d_in[4];
    const float* Wih2 = (const float*)d_in[5];
    const float* Whh2 = (const float*)d_in[6];
    const float* bih2 = (const float*)d_in[7];
    const float* bhh2 = (const float*)d_in[8];
    const float* Wd1  = (const float*)d_in[9];
    const float* bd1  = (const float*)d_in[10];
    const float* Wd2  = (const float*)d_in[11];
    const float* bd2  = (const float*)d_in[12];
    const float* Wd3  = (const float*)d_in[13];
    const float* bd3  = (const float*)d_in[14];
    float* out = (float*)d_out;

    lstm_bf16_kernel<<<1024, 128>>>(x, Wih1, Whh1, bih1, bhh1,
                                    Wih2, Whh2, bih2, bhh2,
                                    Wd1, bd1, Wd2, bd2, Wd3, bd3, out);
}

// round 7
// speedup vs baseline: 1.9401x; 1.9401x over previous
#include <cuda_runtime.h>
#include <cuda_bf16.h>

// Tensor-core LSTM: one warp owns 8 batch elements (rows 0-7 of an m16 tile).
// All four recurrent matmuls per step are mma.sync.m16n8k16 bf16 (8 n-tiles,
// N=64 gates). C-fragment layout == A-fragment layout, so h feeds the next
// step's MMA with two cvt packs; elementwise LSTM is lane-local (4 cells/lane
// per layer). No per-step smem, no shuffles, no syncwarp in the recurrence.

#define FULLMASK 0xffffffffu
#define LOG2E 1.4426950408889634f

typedef unsigned int u32;

static __device__ __forceinline__ u32 packb2(float lo, float hi) {
    u32 d;
    asm("cvt.rn.bf16x2.f32 %0, %1, %2;" : "=r"(d) : "f"(hi), "f"(lo));
    return d;
}
static __device__ __forceinline__ float ex2f(float x) {
    float y; asm("ex2.approx.f32 %0, %1;" : "=f"(y) : "f"(x)); return y;
}
static __device__ __forceinline__ float rcpf(float x) {
    float y; asm("rcp.approx.f32 %0, %1;" : "=f"(y) : "f"(x)); return y;
}
static __device__ __forceinline__ float tanhap(float x) {
    float y; asm("tanh.approx.f32 %0, %1;" : "=f"(y) : "f"(x)); return y;
}

// D += A @ B for one m16n8k16 bf16 tile (accumulate in place, f32)
static __device__ __forceinline__ void mma16816(
    float* d, u32 a0, u32 a1, u32 a2, u32 a3, u32 b0, u32 b1)
{
    asm("mma.sync.aligned.m16n8k16.row.col.f32.bf16.bf16.f32 "
        "{%0,%1,%2,%3},{%4,%5,%6,%7},{%8,%9},{%0,%1,%2,%3};"
        : "+f"(d[0]), "+f"(d[1]), "+f"(d[2]), "+f"(d[3])
        : "r"(a0), "r"(a1), "r"(a2), "r"(a3), "r"(b0), "r"(b1));
}

// one LSTM cell: raw gates -> activations -> cell update -> hidden
#define CELL(IV, FV, GV, OV, CC, HH) do {                                 \
    float si_ = fmaf(0.5f, tanhap(0.5f * (IV)), 0.5f);                    \
    float sf_ = fmaf(0.5f, tanhap(0.5f * (FV)), 0.5f);                    \
    float tg_ = tanhap(GV);                                               \
    float so_ = fmaf(0.5f, tanhap(0.5f * (OV)), 0.5f);                    \
    CC = fmaf(sf_, CC, si_ * tg_);                                        \
    HH = so_ * tanhap(CC);                                                \
} while (0)

__global__ void __launch_bounds__(128)
lstm_mma_kernel(const float* __restrict__ x,
                const float* __restrict__ Wih1, const float* __restrict__ Whh1,
                const float* __restrict__ bih1, const float* __restrict__ bhh1,
                const float* __restrict__ Wih2, const float* __restrict__ Whh2,
                const float* __restrict__ bih2, const float* __restrict__ bhh2,
                const float* __restrict__ Wd1, const float* __restrict__ bd1,
                const float* __restrict__ Wd2, const float* __restrict__ bd2,
                const float* __restrict__ Wd3, const float* __restrict__ bd3,
                float* __restrict__ out)
{
    constexpr int T = 512, IN = 11;
    const int tid  = threadIdx.x;
    const int lane = tid & 31;
    const int wid  = tid >> 5;
    const int q    = lane & 3;       // quad index -> k0/col pair
    const int g    = lane >> 2;      // group -> elem row (A/C), gate col n (B)
    const int k0   = q * 2;
    const int eb   = blockIdx.x * 32;            // CTA batch base (32 elems)

    // x staging: [phase][step-in-chunk][elem][8 bf16x2 = 16 bf16 (K padded)]
    __shared__ __align__(16) u32 xs[2][4][32][8];
    __shared__ float sbuf[32][16];

    // ---- weight B-fragments: per tile t, n = t*8+g; rows k0,k0+1 / k0+8,k0+9
    u32 w1i[8][2], w1h[8][2], w2i[8][2], w2h[8][2];
    float bs1[8][2], bs2[8][2];
#pragma unroll
    for (int t = 0; t < 8; ++t) {
        const int n = t * 8 + g;
        {
            float a0 = Wih1[n * IN + k0];
            float a1 = Wih1[n * IN + k0 + 1];
            float a8 = (k0 + 8 < IN) ? Wih1[n * IN + k0 + 8] : 0.f;
            float a9 = (k0 + 9 < IN) ? Wih1[n * IN + k0 + 9] : 0.f;
            w1i[t][0] = packb2(a0, a1);
            w1i[t][1] = packb2(a8, a9);
        }
        w1h[t][0] = packb2(Whh1[n * 16 + k0],     Whh1[n * 16 + k0 + 1]);
        w1h[t][1] = packb2(Whh1[n * 16 + k0 + 8], Whh1[n * 16 + k0 + 9]);
        w2i[t][0] = packb2(Wih2[n * 16 + k0],     Wih2[n * 16 + k0 + 1]);
        w2i[t][1] = packb2(Wih2[n * 16 + k0 + 8], Wih2[n * 16 + k0 + 9]);
        w2h[t][0] = packb2(Whh2[n * 16 + k0],     Whh2[n * 16 + k0 + 1]);
        w2h[t][1] = packb2(Whh2[n * 16 + k0 + 8], Whh2[n * 16 + k0 + 9]);
        // biases at C columns t*8 + k0, +1 (per-lane slots c0, c1)
        const int col = t * 8 + k0;
        bs1[t][0] = bih1[col]     + bhh1[col];
        bs1[t][1] = bih1[col + 1] + bhh1[col + 1];
        bs2[t][0] = bih2[col]     + bhh2[col];
        bs2[t][1] = bih2[col + 1] + bhh2[col + 1];
    }

    // ---- x staging pointers: thread -> (elem = tid>>2, step-in-chunk = tid&3)
    const int se = tid >> 2;          // CTA-local elem 0..31
    const int ss = tid & 3;           // step within chunk
    const float* xp = x + ((size_t)(eb + se) * T + ss) * IN;

    // stage chunk 0
    {
        float xr[11];
#pragma unroll
        for (int i = 0; i < 11; ++i) xr[i] = __ldg(xp + i);
        u32* d = &xs[0][ss][se][0];
        d[0] = packb2(xr[0], xr[1]); d[1] = packb2(xr[2], xr[3]);
        d[2] = packb2(xr[4], xr[5]); d[3] = packb2(xr[6], xr[7]);
        d[4] = packb2(xr[8], xr[9]); d[5] = packb2(xr[10], 0.f);
        d[6] = 0u; d[7] = 0u;
    }
    __syncwarp();

    const int elw = wid * 8 + g;      // this lane's CTA-local elem

    // recurrent state
    u32 h1a0 = 0, h1a2 = 0, h2a0 = 0, h2a2 = 0;   // h fragments (bf16x2)
    float c10 = 0.f, c11 = 0.f, c12 = 0.f, c13 = 0.f;
    float c20 = 0.f, c21 = 0.f, c22 = 0.f, c23 = 0.f;
    float ss0 = 0.f, ss1 = 0.f, ss2 = 0.f, ss3 = 0.f;
    float h20 = 0.f, h21 = 0.f, h22 = 0.f, h23 = 0.f;

    for (int c = 0; c < 128; ++c) {
        // prefetch next chunk's x (consumed 4 steps later)
        float xr[11];
        if (c < 127) {
            const float* xq = xp + (size_t)(c + 1) * 4 * IN;
#pragma unroll
            for (int i = 0; i < 11; ++i) xr[i] = __ldg(xq + i);
        }

#pragma unroll
        for (int s = 0; s < 4; ++s) {
            const u32* xrow = &xs[c & 1][s][elw][0];
            const u32 xa0 = xrow[q];
            const u32 xa2 = xrow[q + 4];

            // ---- layer 1: acc = bias + Wih1·x + Whh1·h1 ----
            float A[8][4];
#pragma unroll
            for (int t = 0; t < 8; ++t) {
                A[t][0] = bs1[t][0]; A[t][1] = bs1[t][1];
                A[t][2] = bs1[t][0]; A[t][3] = bs1[t][1];
            }
#pragma unroll
            for (int t = 0; t < 8; ++t)
                mma16816(A[t], xa0, xa0, xa2, xa2, w1i[t][0], w1i[t][1]);
#pragma unroll
            for (int t = 0; t < 8; ++t)
                mma16816(A[t], h1a0, h1a0, h1a2, h1a2, w1h[t][0], w1h[t][1]);

            float h10, h11, h12, h13;
            CELL(A[0][0], A[2][0], A[4][0], A[6][0], c10, h10);
            CELL(A[0][1], A[2][1], A[4][1], A[6][1], c11, h11);
            CELL(A[1][0], A[3][0], A[5][0], A[7][0], c12, h12);
            CELL(A[1][1], A[3][1], A[5][1], A[7][1], c13, h13);
            h1a0 = packb2(h10, h11);
            h1a2 = packb2(h12, h13);

            // ---- layer 2: acc = bias + Wih2·h1 + Whh2·h2 ----
            float B[8][4];
#pragma unroll
            for (int t = 0; t < 8; ++t) {
                B[t][0] = bs2[t][0]; B[t][1] = bs2[t][1];
                B[t][2] = bs2[t][0]; B[t][3] = bs2[t][1];
            }
#pragma unroll
            for (int t = 0; t < 8; ++t)
                mma16816(B[t], h1a0, h1a0, h1a2, h1a2, w2i[t][0], w2i[t][1]);
#pragma unroll
            for (int t = 0; t < 8; ++t)
                mma16816(B[t], h2a0, h2a0, h2a2, h2a2, w2h[t][0], w2h[t][1]);

            CELL(B[0][0], B[2][0], B[4][0], B[6][0], c20, h20);
            CELL(B[0][1], B[2][1], B[4][1], B[6][1], c21, h21);
            CELL(B[1][0], B[3][0], B[5][0], B[7][0], c22, h22);
            CELL(B[1][1], B[3][1], B[5][1], B[7][1], c23, h23);
            h2a0 = packb2(h20, h21);
            h2a2 = packb2(h22, h23);

            // time-softmax accumulation: h2 in (-1,1) => max-free
            ss0 += ex2f(h20 * LOG2E);
            ss1 += ex2f(h21 * LOG2E);
            ss2 += ex2f(h22 * LOG2E);
            ss3 += ex2f(h23 * LOG2E);
        }

        // commit prefetched chunk to the other phase buffer
        if (c < 127) {
            u32* d = &xs[(c + 1) & 1][ss][se][0];
            d[0] = packb2(xr[0], xr[1]); d[1] = packb2(xr[2], xr[3]);
            d[2] = packb2(xr[4], xr[5]); d[3] = packb2(xr[6], xr[7]);
            d[4] = packb2(xr[8], xr[9]); d[5] = packb2(xr[10], 0.f);
            d[6] = 0u; d[7] = 0u;
        }
        __syncwarp();
    }

    // ---- epilogue: s = exp(h2_last)/ssum per (elem, hcol) ----
    sbuf[elw][k0]     = ex2f(h20 * LOG2E) * rcpf(ss0);
    sbuf[elw][k0 + 1] = ex2f(h21 * LOG2E) * rcpf(ss1);
    sbuf[elw][k0 + 8] = ex2f(h22 * LOG2E) * rcpf(ss2);
    sbuf[elw][k0 + 9] = ex2f(h23 * LOG2E) * rcpf(ss3);
    __syncwarp();

    // dense head: lanes 0-7 each handle one of the warp's 8 elems
    if (lane < 8) {
        const float* sr = &sbuf[wid * 8 + lane][0];
        float d1[8];
#pragma unroll
        for (int r = 0; r < 8; ++r) {
            float acc = bd1[r];
#pragma unroll
            for (int k = 0; k < 16; ++k)
                acc = fmaf(__ldg(Wd1 + r * 16 + k), sr[k], acc);
            d1[r] = acc;
        }
        float d2[8];
#pragma unroll
        for (int r = 0; r < 8; ++r) {
            float acc = bd2[r];
#pragma unroll
            for (int k = 0; k < 8; ++k)
                acc = fmaf(__ldg(Wd2 + r * 8 + k), d1[k], acc);
            d2[r] = acc;
        }
        float d3[3];
#pragma unroll
        for (int r = 0; r < 3; ++r) {
            float acc = bd3[r];
#pragma unroll
            for (int k = 0; k < 8; ++k)
                acc = fmaf(__ldg(Wd3 + r * 8 + k), d2[k], acc);
            d3[r] = acc;
        }
        float m  = fmaxf(d3[0], fmaxf(d3[1], d3[2]));
        float e0 = ex2f((d3[0] - m) * LOG2E);
        float e1 = ex2f((d3[1] - m) * LOG2E);
        float e2 = ex2f((d3[2] - m) * LOG2E);
        float inv = rcpf(e0 + e1 + e2);
        const int bg = eb + wid * 8 + lane;
        out[bg * 3 + 0] = e0 * inv;
        out[bg * 3 + 1] = e1 * inv;
        out[bg * 3 + 2] = e2 * inv;
    }
}

extern "C" void kernel_launch(void* const* d_in, const int* in_sizes, int n_in,
                              void* d_out, int out_size) {
    (void)in_sizes; (void)n_in; (void)out_size;
    const float* x    = (const float*)d_in[0];
    const float* Wih1 = (const float*)d_in[1];
    const float* Whh1 = (const float*)d_in[2];
    const float* bih1 = (const float*)d_in[3];
    const float* bhh1 = (const float*)d_in[4];
    const float* Wih2 = (const float*)d_in[5];
    const float* Whh2 = (const float*)d_in[6];
    const float* bih2 = (const float*)d_in[7];
    const float* bhh2 = (const float*)d_in[8];
    const float* Wd1  = (const float*)d_in[9];
    const float* bd1  = (const float*)d_in[10];
    const float* Wd2  = (const float*)d_in[11];
    const float* bd2  = (const float*)d_in[12];
    const float* Wd3  = (const float*)d_in[13];
    const float* bd3  = (const float*)d_in[14];
    float* out = (float*)d_out;

    // 4096 elems / (4 warps x 8 elems) = 128 CTAs, ~1 per SM
    lstm_mma_kernel<<<128, 128>>>(x, Wih1, Whh1, bih1, bhh1,
                                  Wih2, Whh2, bih2, bhh2,
                                  Wd1, bd1, Wd2, bd2, Wd3, bd3, out);
}

// round 8
// speedup vs baseline: 2.4841x; 1.2804x over previous
#include <cuda_runtime.h>
#include <cuda_bf16.h>

// Tensor-core LSTM, packed-bf16x2 elementwise path.
// One warp owns 8 batch elements (rows 0-7 of m16 tile, rows 8-15 duplicated).
// mma.sync.m16n8k16 bf16 for all recurrent matmuls (8 n-tiles, N=64 gates).
// Cell math (sigmoid/tanh/cell-update) runs in bf16x2: 2 cells per op, and h
// is produced directly in MMA A-fragment packing (no repack on the rec path).

#define FULLMASK 0xffffffffu
#define LOG2E 1.4426950408889634f
#define H2C 0x3F003F00u   /* bf16x2 {0.5, 0.5} */

typedef unsigned int u32;

static __device__ __forceinline__ u32 packb2(float lo, float hi) {
    u32 d;
    asm("cvt.rn.bf16x2.f32 %0, %1, %2;" : "=r"(d) : "f"(hi), "f"(lo));
    return d;
}
static __device__ __forceinline__ u32 tanhb2(u32 x) {
    u32 y; asm("tanh.approx.bf16x2 %0, %1;" : "=r"(y) : "r"(x)); return y;
}
static __device__ __forceinline__ u32 mulb2(u32 a, u32 b) {
    u32 d; asm("mul.rn.bf16x2 %0, %1, %2;" : "=r"(d) : "r"(a), "r"(b)); return d;
}
static __device__ __forceinline__ u32 fmab2(u32 a, u32 b, u32 c) {
    u32 d; asm("fma.rn.bf16x2 %0, %1, %2, %3;" : "=r"(d) : "r"(a), "r"(b), "r"(c));
    return d;
}
static __device__ __forceinline__ float blo(u32 v) {   // low bf16 -> f32
    return __uint_as_float(v << 16);
}
static __device__ __forceinline__ float bhi(u32 v) {   // high bf16 -> f32
    return __uint_as_float(v & 0xFFFF0000u);
}
static __device__ __forceinline__ float ex2f(float x) {
    float y; asm("ex2.approx.f32 %0, %1;" : "=f"(y) : "f"(x)); return y;
}
static __device__ __forceinline__ float rcpf(float x) {
    float y; asm("rcp.approx.f32 %0, %1;" : "=f"(y) : "f"(x)); return y;
}

// D += A @ B for one m16n8k16 bf16 tile (accumulate in place, f32)
static __device__ __forceinline__ void mma16816(
    float* d, u32 a0, u32 a1, u32 a2, u32 a3, u32 b0, u32 b1)
{
    asm("mma.sync.aligned.m16n8k16.row.col.f32.bf16.bf16.f32 "
        "{%0,%1,%2,%3},{%4,%5,%6,%7},{%8,%9},{%0,%1,%2,%3};"
        : "+f"(d[0]), "+f"(d[1]), "+f"(d[2]), "+f"(d[3])
        : "r"(a0), "r"(a1), "r"(a2), "r"(a3), "r"(b0), "r"(b1));
}

// packed 2-cell LSTM update: gates (bf16x2) -> cell (bf16x2) -> hidden (bf16x2)
// sigmoid(x) = 0.5*tanh(0.5x)+0.5 ; all ops process both cells at once.
#define PCELL(IP, FP, GP, OP, CC, HH) do {                                \
    u32 si_ = fmab2(tanhb2(mulb2((IP), H2C)), H2C, H2C);                  \
    u32 sf_ = fmab2(tanhb2(mulb2((FP), H2C)), H2C, H2C);                  \
    u32 tg_ = tanhb2(GP);                                                 \
    u32 so_ = fmab2(tanhb2(mulb2((OP), H2C)), H2C, H2C);                  \
    CC = fmab2(sf_, CC, mulb2(si_, tg_));                                 \
    HH = mulb2(so_, tanhb2(CC));                                          \
} while (0)

__global__ void __launch_bounds__(128)
lstm_mma_kernel(const float* __restrict__ x,
                const float* __restrict__ Wih1, const float* __restrict__ Whh1,
                const float* __restrict__ bih1, const float* __restrict__ bhh1,
                const float* __restrict__ Wih2, const float* __restrict__ Whh2,
                const float* __restrict__ bih2, const float* __restrict__ bhh2,
                const float* __restrict__ Wd1, const float* __restrict__ bd1,
                const float* __restrict__ Wd2, const float* __restrict__ bd2,
                const float* __restrict__ Wd3, const float* __restrict__ bd3,
                float* __restrict__ out)
{
    constexpr int T = 512, IN = 11;
    const int tid  = threadIdx.x;
    const int lane = tid & 31;
    const int wid  = tid >> 5;
    const int q    = lane & 3;       // quad index -> k0/col pair
    const int g    = lane >> 2;      // group -> elem row (A/C), gate col n (B)
    const int k0   = q * 2;
    const int eb   = blockIdx.x * 32;            // CTA batch base (32 elems)

    // x staging: [phase][step-in-chunk][elem][8 bf16x2 = 16 bf16 (K padded)]
    __shared__ __align__(16) u32 xs[2][4][32][8];
    __shared__ float sbuf[32][16];

    // ---- weight B-fragments: per tile t, n = t*8+g; rows k0,k0+1 / k0+8,k0+9
    u32 w1i[8][2], w1h[8][2], w2i[8][2], w2h[8][2];
    float bs1[8][2], bs2[8][2];
#pragma unroll
    for (int t = 0; t < 8; ++t) {
        const int n = t * 8 + g;
        {
            float a0 = Wih1[n * IN + k0];
            float a1 = Wih1[n * IN + k0 + 1];
            float a8 = (k0 + 8 < IN) ? Wih1[n * IN + k0 + 8] : 0.f;
            float a9 = (k0 + 9 < IN) ? Wih1[n * IN + k0 + 9] : 0.f;
            w1i[t][0] = packb2(a0, a1);
            w1i[t][1] = packb2(a8, a9);
        }
        w1h[t][0] = packb2(Whh1[n * 16 + k0],     Whh1[n * 16 + k0 + 1]);
        w1h[t][1] = packb2(Whh1[n * 16 + k0 + 8], Whh1[n * 16 + k0 + 9]);
        w2i[t][0] = packb2(Wih2[n * 16 + k0],     Wih2[n * 16 + k0 + 1]);
        w2i[t][1] = packb2(Wih2[n * 16 + k0 + 8], Wih2[n * 16 + k0 + 9]);
        w2h[t][0] = packb2(Whh2[n * 16 + k0],     Whh2[n * 16 + k0 + 1]);
        w2h[t][1] = packb2(Whh2[n * 16 + k0 + 8], Whh2[n * 16 + k0 + 9]);
        // biases at C columns t*8 + k0, +1 (per-lane slots c0, c1)
        const int col = t * 8 + k0;
        bs1[t][0] = bih1[col]     + bhh1[col];
        bs1[t][1] = bih1[col + 1] + bhh1[col + 1];
        bs2[t][0] = bih2[col]     + bhh2[col];
        bs2[t][1] = bih2[col + 1] + bhh2[col + 1];
    }

    // ---- x staging pointers: thread -> (elem = tid>>2, step-in-chunk = tid&3)
    const int se = tid >> 2;          // CTA-local elem 0..31
    const int ss = tid & 3;           // step within chunk
    const float* xp = x + ((size_t)(eb + se) * T + ss) * IN;

    // stage chunk 0
    {
        float xr[11];
#pragma unroll
        for (int i = 0; i < 11; ++i) xr[i] = __ldg(xp + i);
        u32* d = &xs[0][ss][se][0];
        d[0] = packb2(xr[0], xr[1]); d[1] = packb2(xr[2], xr[3]);
        d[2] = packb2(xr[4], xr[5]); d[3] = packb2(xr[6], xr[7]);
        d[4] = packb2(xr[8], xr[9]); d[5] = packb2(xr[10], 0.f);
        d[6] = 0u; d[7] = 0u;
    }
    __syncwarp();

    const int elw = wid * 8 + g;      // this lane's CTA-local elem

    // recurrent state (all packed bf16x2: {cell 2q, cell 2q+1} etc.)
    u32 h1a0 = 0, h1a2 = 0, h2a0 = 0, h2a2 = 0;
    u32 c1p0 = 0, c1p1 = 0, c2p0 = 0, c2p1 = 0;
    float ss0 = 0.f, ss1 = 0.f, ss2 = 0.f, ss3 = 0.f;

    for (int c = 0; c < 128; ++c) {
        // prefetch next chunk's x (consumed 4 steps later)
        float xr[11];
        if (c < 127) {
            const float* xq = xp + (size_t)(c + 1) * 4 * IN;
#pragma unroll
            for (int i = 0; i < 11; ++i) xr[i] = __ldg(xq + i);
        }

#pragma unroll
        for (int s = 0; s < 4; ++s) {
            const u32* xrow = &xs[c & 1][s][elw][0];
            const u32 xa0 = xrow[q];
            const u32 xa2 = xrow[q + 4];

            // ---- layer 1: acc = bias + Wih1·x + Whh1·h1 ----
            float A[8][4];
#pragma unroll
            for (int t = 0; t < 8; ++t) {
                A[t][0] = bs1[t][0]; A[t][1] = bs1[t][1];
                A[t][2] = bs1[t][0]; A[t][3] = bs1[t][1];
            }
#pragma unroll
            for (int t = 0; t < 8; ++t)
                mma16816(A[t], xa0, xa0, xa2, xa2, w1i[t][0], w1i[t][1]);
#pragma unroll
            for (int t = 0; t < 8; ++t)
                mma16816(A[t], h1a0, h1a0, h1a2, h1a2, w1h[t][0], w1h[t][1]);

            // pack gates into bf16x2 pairs; tiles {0,1}=i {2,3}=f {4,5}=g {6,7}=o
            {
                u32 iP0 = packb2(A[0][0], A[0][1]), iP1 = packb2(A[1][0], A[1][1]);
                u32 fP0 = packb2(A[2][0], A[2][1]), fP1 = packb2(A[3][0], A[3][1]);
                u32 gP0 = packb2(A[4][0], A[4][1]), gP1 = packb2(A[5][0], A[5][1]);
                u32 oP0 = packb2(A[6][0], A[6][1]), oP1 = packb2(A[7][0], A[7][1]);
                PCELL(iP0, fP0, gP0, oP0, c1p0, h1a0);   // h1a0 = A-frag a0 direct
                PCELL(iP1, fP1, gP1, oP1, c1p1, h1a2);   // h1a2 = A-frag a2 direct
            }

            // ---- layer 2: acc = bias + Wih2·h1 + Whh2·h2 ----
            float B[8][4];
#pragma unroll
            for (int t = 0; t < 8; ++t) {
                B[t][0] = bs2[t][0]; B[t][1] = bs2[t][1];
                B[t][2] = bs2[t][0]; B[t][3] = bs2[t][1];
            }
#pragma unroll
            for (int t = 0; t < 8; ++t)
                mma16816(B[t], h1a0, h1a0, h1a2, h1a2, w2i[t][0], w2i[t][1]);
#pragma unroll
            for (int t = 0; t < 8; ++t)
                mma16816(B[t], h2a0, h2a0, h2a2, h2a2, w2h[t][0], w2h[t][1]);

            {
                u32 iP0 = packb2(B[0][0], B[0][1]), iP1 = packb2(B[1][0], B[1][1]);
                u32 fP0 = packb2(B[2][0], B[2][1]), fP1 = packb2(B[3][0], B[3][1]);
                u32 gP0 = packb2(B[4][0], B[4][1]), gP1 = packb2(B[5][0], B[5][1]);
                u32 oP0 = packb2(B[6][0], B[6][1]), oP1 = packb2(B[7][0], B[7][1]);
                PCELL(iP0, fP0, gP0, oP0, c2p0, h2a0);
                PCELL(iP1, fP1, gP1, oP1, c2p1, h2a2);
            }

            // time-softmax accumulation: h2 in (-1,1) => max-free
            ss0 += ex2f(blo(h2a0) * LOG2E);
            ss1 += ex2f(bhi(h2a0) * LOG2E);
            ss2 += ex2f(blo(h2a2) * LOG2E);
            ss3 += ex2f(bhi(h2a2) * LOG2E);
        }

        // commit prefetched chunk to the other phase buffer
        if (c < 127) {
            u32* d = &xs[(c + 1) & 1][ss][se][0];
            d[0] = packb2(xr[0], xr[1]); d[1] = packb2(xr[2], xr[3]);
            d[2] = packb2(xr[4], xr[5]); d[3] = packb2(xr[6], xr[7]);
            d[4] = packb2(xr[8], xr[9]); d[5] = packb2(xr[10], 0.f);
            d[6] = 0u; d[7] = 0u;
        }
        __syncwarp();
    }

    // ---- epilogue: s = exp(h2_last)/ssum per (elem, hcol) ----
    sbuf[elw][k0]     = ex2f(blo(h2a0) * LOG2E) * rcpf(ss0);
    sbuf[elw][k0 + 1] = ex2f(bhi(h2a0) * LOG2E) * rcpf(ss1);
    sbuf[elw][k0 + 8] = ex2f(blo(h2a2) * LOG2E) * rcpf(ss2);
    sbuf[elw][k0 + 9] = ex2f(bhi(h2a2) * LOG2E) * rcpf(ss3);
    __syncwarp();

    // dense head: lanes 0-7 each handle one of the warp's 8 elems
    if (lane < 8) {
        const float* sr = &sbuf[wid * 8 + lane][0];
        float d1[8];
#pragma unroll
        for (int r = 0; r < 8; ++r) {
            float acc = bd1[r];
#pragma unroll
            for (int k = 0; k < 16; ++k)
                acc = fmaf(__ldg(Wd1 + r * 16 + k), sr[k], acc);
            d1[r] = acc;
        }
        float d2[8];
#pragma unroll
        for (int r = 0; r < 8; ++r) {
            float acc = bd2[r];
#pragma unroll
            for (int k = 0; k < 8; ++k)
                acc = fmaf(__ldg(Wd2 + r * 8 + k), d1[k], acc);
            d2[r] = acc;
        }
        float d3[3];
#pragma unroll
        for (int r = 0; r < 3; ++r) {
            float acc = bd3[r];
#pragma unroll
            for (int k = 0; k < 8; ++k)
                acc = fmaf(__ldg(Wd3 + r * 8 + k), d2[k], acc);
            d3[r] = acc;
        }
        float m  = fmaxf(d3[0], fmaxf(d3[1], d3[2]));
        float e0 = ex2f((d3[0] - m) * LOG2E);
        float e1 = ex2f((d3[1] - m) * LOG2E);
        float e2 = ex2f((d3[2] - m) * LOG2E);
        float inv = rcpf(e0 + e1 + e2);
        const int bg = eb + wid * 8 + lane;
        out[bg * 3 + 0] = e0 * inv;
        out[bg * 3 + 1] = e1 * inv;
        out[bg * 3 + 2] = e2 * inv;
    }
}

extern "C" void kernel_launch(void* const* d_in, const int* in_sizes, int n_in,
                              void* d_out, int out_size) {
    (void)in_sizes; (void)n_in; (void)out_size;
    const float* x    = (const float*)d_in[0];
    const float* Wih1 = (const float*)d_in[1];
    const float* Whh1 = (const float*)d_in[2];
    const float* bih1 = (const float*)d_in[3];
    const float* bhh1 = (const float*)d_in[4];
    const float* Wih2 = (const float*)d_in[5];
    const float* Whh2 = (const float*)d_in[6];
    const float* bih2 = (const float*)d_in[7];
    const float* bhh2 = (const float*)d_in[8];
    const float* Wd1  = (const float*)d_in[9];
    const float* bd1  = (const float*)d_in[10];
    const float* Wd2  = (const float*)d_in[11];
    const float* bd2  = (const float*)d_in[12];
    const float* Wd3  = (const float*)d_in[13];
    const float* bd3  = (const float*)d_in[14];
    float* out = (float*)d_out;

    // 4096 elems / (4 warps x 8 elems) = 128 CTAs
    lstm_mma_kernel<<<128, 128>>>(x, Wih1, Whh1, bih1, bhh1,
                                  Wih2, Whh2, bih2, bhh2,
                                  Wd1, bd1, Wd2, bd2, Wd3, bd3, out);
}